// round 1
// baseline (speedup 1.0000x reference)
#include <cuda_runtime.h>

// x: [b=2, c=64, d=16, h=16, w=16, p=4, q=4, r=4] fp32, row-major.
// Element strides: r=1, q=4, p=16, w=64, h=1024, d=16384, c=262144, b=16777216.
// Each axial op: out[m, o] = sum_k x_gather[m, k] * W[o, k] + bias[o]
//   with k = s_in*64 + c_in, o = s_out*64 + c_out (channel fastest).
// Six ops accumulate into g_acc; final kernel: y = x + leaky_relu(g_acc).

#define TOTAL_ELEMS 33554432
#define STR_C 262144

__device__ float g_acc[TOTAL_ELEMS];

struct Dims6 { int size[6]; int stride[6]; };

// 128x128 output tile, K-tile = 8, 256 threads, 8x8 per-thread micro-tile.
__global__ __launch_bounds__(256, 2)
void axial_gemm(const float* __restrict__ X,
                const float* __restrict__ W,
                const float* __restrict__ Bias,
                Dims6 dims, int n, int str_a, int first)
{
    __shared__ float As[8][128];
    __shared__ float Bs[8][132];     // padded: conflict-free stores
    __shared__ float Cs[128 * 17];   // padded epilogue staging
    __shared__ int   base_s[128];

    const int tid = threadIdx.x;
    const int bx = blockIdx.x, bn = blockIdx.y;

    // Base global offset for each of the 128 positions in this M-tile.
    if (tid < 128) {
        int m = bx * 128 + tid;
        int off = 0;
        #pragma unroll
        for (int j = 0; j < 6; j++) {
            off += (m % dims.size[j]) * dims.stride[j];
            m /= dims.size[j];
        }
        base_s[tid] = off;
    }
    __syncthreads();

    const int tx = tid & 15, ty = tid >> 4;

    float acc[8][8];
    #pragma unroll
    for (int i = 0; i < 8; i++)
        #pragma unroll
        for (int j = 0; j < 8; j++) acc[i][j] = 0.f;

    // A-load mapping: 128 m x 8 k, 4 loads/thread, consecutive tid -> consecutive m.
    const int mA  = tid & 127;
    const int kA0 = tid >> 7;        // 0 or 1
    const int baseA = base_s[mA];

    // B-load mapping: each thread loads 4 consecutive k of one output row (float4).
    const int oB  = bn * 128 + (tid >> 1);
    const int kB0 = (tid & 1) * 4;
    const int oBl = tid >> 1;

    const int nk = n >> 3;
    for (int kt = 0; kt < nk; kt++) {
        const int k0 = kt << 3;
        const int s_cur = k0 >> 6;        // K-tile never crosses an s boundary (8 | 64)
        const int cc0   = k0 & 63;
        const int aoff = baseA + s_cur * str_a + cc0 * STR_C;

        float a_reg[4];
        #pragma unroll
        for (int j = 0; j < 4; j++)
            a_reg[j] = X[aoff + (kA0 + 2 * j) * STR_C];
        float4 b_reg = *reinterpret_cast<const float4*>(&W[(long)oB * n + k0 + kB0]);

        __syncthreads();   // previous tile's compute finished
        #pragma unroll
        for (int j = 0; j < 4; j++) As[kA0 + 2 * j][mA] = a_reg[j];
        Bs[kB0 + 0][oBl] = b_reg.x;
        Bs[kB0 + 1][oBl] = b_reg.y;
        Bs[kB0 + 2][oBl] = b_reg.z;
        Bs[kB0 + 3][oBl] = b_reg.w;
        __syncthreads();

        #pragma unroll
        for (int kk = 0; kk < 8; kk++) {
            float4 a0 = *reinterpret_cast<float4*>(&As[kk][ty * 8]);
            float4 a1 = *reinterpret_cast<float4*>(&As[kk][ty * 8 + 4]);
            float4 b0 = *reinterpret_cast<float4*>(&Bs[kk][tx * 8]);
            float4 b1 = *reinterpret_cast<float4*>(&Bs[kk][tx * 8 + 4]);
            float av[8] = {a0.x, a0.y, a0.z, a0.w, a1.x, a1.y, a1.z, a1.w};
            float bv[8] = {b0.x, b0.y, b0.z, b0.w, b1.x, b1.y, b1.z, b1.w};
            #pragma unroll
            for (int i = 0; i < 8; i++)
                #pragma unroll
                for (int j = 0; j < 8; j++)
                    acc[i][j] += av[i] * bv[j];
        }
    }

    // Epilogue: stage through smem so global RMW is coalesced along m.
    const int lane = tid & 31, wrp = tid >> 5;
    for (int os = 0; os < 8; os++) {           // 8 slices of 16 output columns
        __syncthreads();
        if ((tx >> 1) == os) {
            const int oin_base = (tx & 1) * 8;
            #pragma unroll
            for (int mi = 0; mi < 8; mi++)
                #pragma unroll
                for (int ni = 0; ni < 8; ni++)
                    Cs[(ty * 8 + mi) * 17 + oin_base + ni] = acc[mi][ni];
        }
        __syncthreads();
        #pragma unroll
        for (int pass = 0; pass < 2; pass++) {
            const int o_in = wrp + pass * 8;
            const int o = bn * 128 + os * 16 + o_in;
            const int so = o >> 6, co = o & 63;
            const float bias = Bias[o];
            const int ooff = so * str_a + co * STR_C;
            #pragma unroll
            for (int j = 0; j < 4; j++) {
                const int m = lane + 32 * j;
                const float v = Cs[m * 17 + o_in] + bias;
                const int addr = base_s[m] + ooff;
                if (first) g_acc[addr] = v;
                else       g_acc[addr] += v;
            }
        }
    }
}

__global__ void finalize_kernel(const float4* __restrict__ X, float4* __restrict__ Y)
{
    const int i = blockIdx.x * blockDim.x + threadIdx.x;
    const float4* A = reinterpret_cast<const float4*>(g_acc);
    float4 x = X[i];
    float4 a = A[i];
    float4 y;
    y.x = x.x + (a.x > 0.f ? a.x : 0.01f * a.x);
    y.y = x.y + (a.y > 0.f ? a.y : 0.01f * a.y);
    y.z = x.z + (a.z > 0.f ? a.z : 0.01f * a.z);
    y.w = x.w + (a.w > 0.f ? a.w : 0.01f * a.w);
    Y[i] = y;
}

extern "C" void kernel_launch(void* const* d_in, const int* in_sizes, int n_in,
                              void* d_out, int out_size)
{
    const float* x    = (const float*)d_in[0];
    const float* w_d  = (const float*)d_in[1];
    const float* b_d  = (const float*)d_in[2];
    const float* w_h  = (const float*)d_in[3];
    const float* b_h  = (const float*)d_in[4];
    const float* w_w  = (const float*)d_in[5];
    const float* b_w  = (const float*)d_in[6];
    const float* w_pd = (const float*)d_in[7];
    const float* b_pd = (const float*)d_in[8];
    const float* w_ph = (const float*)d_in[9];
    const float* b_ph = (const float*)d_in[10];
    const float* w_pw = (const float*)d_in[11];
    const float* b_pw = (const float*)d_in[12];

    // Remaining-dims (size, stride) for each axis, fastest-stride first.
    // Full dims: b(2,16777216) c(64,262144) d(16,16384) h(16,1024) w(16,64) p(4,16) q(4,4) r(4,1)
    Dims6 dD = {{4,4,4,16,16,2},   {1,4,16,64,1024,16777216}};      // axis d
    Dims6 dH = {{4,4,4,16,16,2},   {1,4,16,64,16384,16777216}};     // axis h
    Dims6 dW = {{4,4,4,16,16,2},   {1,4,16,1024,16384,16777216}};   // axis w
    Dims6 dP = {{4,4,16,16,16,2},  {1,4,64,1024,16384,16777216}};   // axis p
    Dims6 dQ = {{4,4,16,16,16,2},  {1,16,64,1024,16384,16777216}};  // axis q
    Dims6 dR = {{4,4,16,16,16,2},  {4,16,64,1024,16384,16777216}};  // axis r

    // Patch ops: M=131072 -> grid.x=1024, n=256 -> grid.y=2
    // Image ops: M=32768  -> grid.x=256,  n=1024 -> grid.y=8
    axial_gemm<<<dim3(1024, 2), 256>>>(x, w_pd, b_pd, dP, 256, 16,    1);
    axial_gemm<<<dim3(1024, 2), 256>>>(x, w_ph, b_ph, dQ, 256, 4,     0);
    axial_gemm<<<dim3(1024, 2), 256>>>(x, w_pw, b_pw, dR, 256, 1,     0);
    axial_gemm<<<dim3(256,  8), 256>>>(x, w_d,  b_d,  dD, 1024, 16384, 0);
    axial_gemm<<<dim3(256,  8), 256>>>(x, w_h,  b_h,  dH, 1024, 1024,  0);
    axial_gemm<<<dim3(256,  8), 256>>>(x, w_w,  b_w,  dW, 1024, 64,    0);

    finalize_kernel<<<TOTAL_ELEMS / 4 / 256, 256>>>(
        (const float4*)x, (float4*)d_out);
}

// round 3
// speedup vs baseline: 2.0523x; 2.0523x over previous
#include <cuda_runtime.h>
#include <cuda_bf16.h>
#include <cstdint>

#define TOTAL_ELEMS 33554432
#define STR_C 262144

__device__ float g_acc[TOTAL_ELEMS];

struct Dims6 { int size[6]; int stride[6]; };

// smem: rows of 32 bf16 (64B) padded to 80B -> ldmatrix & LDS conflict-free.
#define ROWB 80
#define MATB (128 * ROWB)          // one 128-row matrix = 10240 B
#define A_HI 0
#define A_LO (1 * MATB)
#define B_HI (2 * MATB)
#define B_LO (3 * MATB)
#define BUF_TOTAL (4 * MATB)       // 40960 B per buffer
#define DYN_SMEM (2 * BUF_TOTAL)   // 81920 B

__device__ __forceinline__ uint32_t smem_u32(const void* p) {
    uint32_t a;
    asm("{ .reg .u64 t; cvta.to.shared.u64 t, %1; cvt.u32.u64 %0, t; }" : "=r"(a) : "l"(p));
    return a;
}
__device__ __forceinline__ void ldsm4(uint32_t* r, uint32_t a) {
    asm volatile("ldmatrix.sync.aligned.m8n8.x4.shared.b16 {%0,%1,%2,%3}, [%4];"
        : "=r"(r[0]), "=r"(r[1]), "=r"(r[2]), "=r"(r[3]) : "r"(a));
}
__device__ __forceinline__ void mma16816(float* d, const uint32_t* a, const uint32_t* b) {
    asm volatile("mma.sync.aligned.m16n8k16.row.col.f32.bf16.bf16.f32 "
        "{%0,%1,%2,%3}, {%4,%5,%6,%7}, {%8,%9}, {%0,%1,%2,%3};"
        : "+f"(d[0]), "+f"(d[1]), "+f"(d[2]), "+f"(d[3])
        : "r"(a[0]), "r"(a[1]), "r"(a[2]), "r"(a[3]), "r"(b[0]), "r"(b[1]));
}
__device__ __forceinline__ uint32_t packbf(__nv_bfloat16 lo, __nv_bfloat16 hi) {
    return ((uint32_t)__bfloat16_as_ushort(hi) << 16) | __bfloat16_as_ushort(lo);
}
// split v -> (hi packed pair, lo packed pair)
__device__ __forceinline__ void split2(float v0, float v1, uint32_t& hp, uint32_t& lp) {
    __nv_bfloat16 h0 = __float2bfloat16(v0);
    __nv_bfloat16 h1 = __float2bfloat16(v1);
    __nv_bfloat16 l0 = __float2bfloat16(v0 - __bfloat162float(h0));
    __nv_bfloat16 l1 = __float2bfloat16(v1 - __bfloat162float(h1));
    hp = packbf(h0, h1);
    lp = packbf(l0, l1);
}

// CTA tile 128m x 128n, BK=32. 8 warps: warp_m = wid>>2 (64 rows), warp_n = wid&3 (32 cols).
__global__ __launch_bounds__(256, 1)
void axial_mma(const float* __restrict__ X, const float* __restrict__ W,
               const float* __restrict__ Bias, Dims6 dims,
               int n, int str_a, int first)
{
    extern __shared__ __align__(16) char dsm[];
    __shared__ int base_s[128];

    const int tid = threadIdx.x;
    const int lane = tid & 31, wid = tid >> 5;
    const int nb = blockIdx.x;          // N-block fastest: A shared in L2 across wave
    const int bx = blockIdx.y;
    const int warp_m = wid >> 2, warp_n = wid & 3;

    if (tid < 128) {
        int m = bx * 128 + tid;
        int off = 0;
        #pragma unroll
        for (int j = 0; j < 6; j++) { off += (m % dims.size[j]) * dims.stride[j]; m /= dims.size[j]; }
        base_s[tid] = off;
    }
    __syncthreads();

    const uint32_t sb = smem_u32(dsm);

    // ldmatrix per-lane base offsets (within a matrix)
    const uint32_t a_lm = (uint32_t)((warp_m * 64 + (lane & 15)) * ROWB + (lane >> 4) * 16);
    const uint32_t b_lm = (uint32_t)((warp_n * 32 + ((lane >> 4) & 1) * 8 + (lane & 7)) * ROWB
                                     + ((lane >> 3) & 1) * 16);

    // global-load mappings
    const int mA = tid & 127, halfA = tid >> 7;            // A: 16 c-values each
    const float* apX = X + base_s[mA];
    const int k4B = (tid & 7) * 4, oB0 = tid >> 3;         // B: 4 float4 each
    const float* wpX = W + (size_t)(nb * 128 + oB0) * n + k4B;

    float acc[4][4][4];
    #pragma unroll
    for (int i = 0; i < 4; i++)
        #pragma unroll
        for (int j = 0; j < 4; j++)
            #pragma unroll
            for (int q = 0; q < 4; q++) acc[i][j][q] = 0.f;

    const int nk = n >> 5;
    float aV[16];
    float4 bV[4];

    // ---- load chunk 0 ----
    {
        const float* ap = apX + (halfA * 16) * STR_C;
        #pragma unroll
        for (int e = 0; e < 16; e++) aV[e] = __ldg(ap + e * STR_C);
        #pragma unroll
        for (int j = 0; j < 4; j++)
            bV[j] = *(const float4*)(wpX + (size_t)(j * 32) * n);
    }
    // ---- store chunk 0 -> buf 0 ----
    {
        char* bp = dsm;
        const uint32_t ar = (uint32_t)(mA * ROWB);
        #pragma unroll
        for (int j = 0; j < 8; j++) {
            const int kc = halfA * 16 + 2 * j;
            uint32_t hp, lp; split2(aV[2 * j], aV[2 * j + 1], hp, lp);
            *(uint32_t*)(bp + A_HI + ar + kc * 2) = hp;
            *(uint32_t*)(bp + A_LO + ar + kc * 2) = lp;
        }
        #pragma unroll
        for (int j = 0; j < 4; j++) {
            const uint32_t br = (uint32_t)((oB0 + j * 32) * ROWB + k4B * 2);
            uint32_t h0, l0, h1, l1;
            split2(bV[j].x, bV[j].y, h0, l0);
            split2(bV[j].z, bV[j].w, h1, l1);
            *(uint32_t*)(bp + B_HI + br)     = h0;
            *(uint32_t*)(bp + B_HI + br + 4) = h1;
            *(uint32_t*)(bp + B_LO + br)     = l0;
            *(uint32_t*)(bp + B_LO + br + 4) = l1;
        }
    }
    __syncthreads();

    for (int ch = 0; ch < nk; ch++) {
        // ---- prefetch next chunk into regs ----
        if (ch + 1 < nk) {
            const int nc = ch + 1;
            const float* ap = apX + (nc >> 1) * str_a
                            + (((nc & 1) << 5) + halfA * 16) * STR_C;
            #pragma unroll
            for (int e = 0; e < 16; e++) aV[e] = __ldg(ap + e * STR_C);
            const float* wp = wpX + nc * 32;
            #pragma unroll
            for (int j = 0; j < 4; j++)
                bV[j] = *(const float4*)(wp + (size_t)(j * 32) * n);
        }

        // ---- compute from buf ch&1 ----
        {
            const uint32_t ab = sb + (uint32_t)((ch & 1) * BUF_TOTAL);
            #pragma unroll
            for (int ka = 0; ka < 2; ka++) {
                const uint32_t koff = (uint32_t)(ka * 32);
                uint32_t ah[4][4], al[4][4], bh[4][2], bl[4][2];
                #pragma unroll
                for (int mt = 0; mt < 4; mt++)
                    ldsm4(ah[mt], ab + A_HI + a_lm + mt * (16 * ROWB) + koff);
                #pragma unroll
                for (int mt = 0; mt < 4; mt++)
                    ldsm4(al[mt], ab + A_LO + a_lm + mt * (16 * ROWB) + koff);
                #pragma unroll
                for (int p = 0; p < 2; p++) {
                    uint32_t r[4];
                    ldsm4(r, ab + B_HI + b_lm + p * (16 * ROWB) + koff);
                    bh[2 * p][0] = r[0]; bh[2 * p][1] = r[1];
                    bh[2 * p + 1][0] = r[2]; bh[2 * p + 1][1] = r[3];
                }
                #pragma unroll
                for (int mt = 0; mt < 4; mt++)
                    #pragma unroll
                    for (int nt = 0; nt < 4; nt++)
                        mma16816(acc[mt][nt], ah[mt], bh[nt]);
                #pragma unroll
                for (int mt = 0; mt < 4; mt++)
                    #pragma unroll
                    for (int nt = 0; nt < 4; nt++)
                        mma16816(acc[mt][nt], al[mt], bh[nt]);
                #pragma unroll
                for (int p = 0; p < 2; p++) {
                    uint32_t r[4];
                    ldsm4(r, ab + B_LO + b_lm + p * (16 * ROWB) + koff);
                    bl[2 * p][0] = r[0]; bl[2 * p][1] = r[1];
                    bl[2 * p + 1][0] = r[2]; bl[2 * p + 1][1] = r[3];
                }
                #pragma unroll
                for (int mt = 0; mt < 4; mt++)
                    #pragma unroll
                    for (int nt = 0; nt < 4; nt++)
                        mma16816(acc[mt][nt], ah[mt], bl[nt]);
            }
        }

        // ---- store prefetched chunk -> other buffer ----
        if (ch + 1 < nk) {
            char* bp = dsm + ((ch + 1) & 1) * BUF_TOTAL;
            const uint32_t ar = (uint32_t)(mA * ROWB);
            #pragma unroll
            for (int j = 0; j < 8; j++) {
                const int kc = halfA * 16 + 2 * j;
                uint32_t hp, lp; split2(aV[2 * j], aV[2 * j + 1], hp, lp);
                *(uint32_t*)(bp + A_HI + ar + kc * 2) = hp;
                *(uint32_t*)(bp + A_LO + ar + kc * 2) = lp;
            }
            #pragma unroll
            for (int j = 0; j < 4; j++) {
                const uint32_t br = (uint32_t)((oB0 + j * 32) * ROWB + k4B * 2);
                uint32_t h0, l0, h1, l1;
                split2(bV[j].x, bV[j].y, h0, l0);
                split2(bV[j].z, bV[j].w, h1, l1);
                *(uint32_t*)(bp + B_HI + br)     = h0;
                *(uint32_t*)(bp + B_HI + br + 4) = h1;
                *(uint32_t*)(bp + B_LO + br)     = l0;
                *(uint32_t*)(bp + B_LO + br + 4) = l1;
            }
            __syncthreads();
        }
    }

    // ---- epilogue: d-frag -> g_acc (RMW unless first) ----
    {
        const int r0 = lane >> 2;
        const int cp = (lane & 3) * 2;
        #pragma unroll
        for (int mt = 0; mt < 4; mt++) {
            const int ml = warp_m * 64 + mt * 16 + r0;
            const int mb0 = base_s[ml];
            const int mb1 = base_s[ml + 8];
            #pragma unroll
            for (int nt = 0; nt < 4; nt++) {
                const int o = nb * 128 + warp_n * 32 + nt * 8 + cp;
                const int ooff = (o >> 6) * str_a + (o & 63) * STR_C;
                const float bi0 = __ldg(Bias + o);
                const float bi1 = __ldg(Bias + o + 1);
                float* g0 = g_acc + mb0 + ooff;
                float* g1 = g_acc + mb1 + ooff;
                if (first) {
                    g0[0]     = acc[mt][nt][0] + bi0;
                    g0[STR_C] = acc[mt][nt][1] + bi1;
                    g1[0]     = acc[mt][nt][2] + bi0;
                    g1[STR_C] = acc[mt][nt][3] + bi1;
                } else {
                    g0[0]     += acc[mt][nt][0] + bi0;
                    g0[STR_C] += acc[mt][nt][1] + bi1;
                    g1[0]     += acc[mt][nt][2] + bi0;
                    g1[STR_C] += acc[mt][nt][3] + bi1;
                }
            }
        }
    }
}

__global__ void finalize_kernel(const float4* __restrict__ X, float4* __restrict__ Y)
{
    const int i = blockIdx.x * blockDim.x + threadIdx.x;
    const float4* A = reinterpret_cast<const float4*>(g_acc);
    float4 x = X[i];
    float4 a = A[i];
    float4 y;
    y.x = x.x + (a.x > 0.f ? a.x : 0.01f * a.x);
    y.y = x.y + (a.y > 0.f ? a.y : 0.01f * a.y);
    y.z = x.z + (a.z > 0.f ? a.z : 0.01f * a.z);
    y.w = x.w + (a.w > 0.f ? a.w : 0.01f * a.w);
    Y[i] = y;
}

extern "C" void kernel_launch(void* const* d_in, const int* in_sizes, int n_in,
                              void* d_out, int out_size)
{
    const float* x    = (const float*)d_in[0];
    const float* w_d  = (const float*)d_in[1];
    const float* b_d  = (const float*)d_in[2];
    const float* w_h  = (const float*)d_in[3];
    const float* b_h  = (const float*)d_in[4];
    const float* w_w  = (const float*)d_in[5];
    const float* b_w  = (const float*)d_in[6];
    const float* w_pd = (const float*)d_in[7];
    const float* b_pd = (const float*)d_in[8];
    const float* w_ph = (const float*)d_in[9];
    const float* b_ph = (const float*)d_in[10];
    const float* w_pw = (const float*)d_in[11];
    const float* b_pw = (const float*)d_in[12];

    cudaFuncSetAttribute(axial_mma, cudaFuncAttributeMaxDynamicSharedMemorySize, DYN_SMEM);

    // Full dims: b(2,16777216) c(64,262144) d(16,16384) h(16,1024) w(16,64) p(4,16) q(4,4) r(4,1)
    Dims6 dD = {{4,4,4,16,16,2},   {1,4,16,64,1024,16777216}};      // axis d
    Dims6 dH = {{4,4,4,16,16,2},   {1,4,16,64,16384,16777216}};     // axis h
    Dims6 dW = {{4,4,4,16,16,2},   {1,4,16,1024,16384,16777216}};   // axis w
    Dims6 dP = {{4,4,16,16,16,2},  {1,4,64,1024,16384,16777216}};   // axis p
    Dims6 dQ = {{4,4,16,16,16,2},  {1,16,64,1024,16384,16777216}};  // axis q
    Dims6 dR = {{4,4,16,16,16,2},  {4,16,64,1024,16384,16777216}};  // axis r

    // grid = (n_blocks, m_blocks): N fastest so concurrent CTAs share A in L2.
    axial_mma<<<dim3(2, 1024), 256, DYN_SMEM>>>(x, w_pd, b_pd, dP, 256, 16,    1);
    axial_mma<<<dim3(2, 1024), 256, DYN_SMEM>>>(x, w_ph, b_ph, dQ, 256, 4,     0);
    axial_mma<<<dim3(2, 1024), 256, DYN_SMEM>>>(x, w_pw, b_pw, dR, 256, 1,     0);
    axial_mma<<<dim3(8, 256),  256, DYN_SMEM>>>(x, w_d,  b_d,  dD, 1024, 16384, 0);
    axial_mma<<<dim3(8, 256),  256, DYN_SMEM>>>(x, w_h,  b_h,  dH, 1024, 1024,  0);
    axial_mma<<<dim3(8, 256),  256, DYN_SMEM>>>(x, w_w,  b_w,  dW, 1024, 64,    0);

    finalize_kernel<<<TOTAL_ELEMS / 4 / 256, 256>>>(
        (const float4*)x, (float4*)d_out);
}

// round 4
// speedup vs baseline: 2.7368x; 1.3335x over previous
#include <cuda_runtime.h>
#include <cuda_bf16.h>
#include <cstdint>

#define TOTAL_ELEMS 33554432
#define NROWS 524288              // (b,s) rows, 64 c each

__device__ __align__(128) float g_acc[TOTAL_ELEMS];
__device__ __align__(128) __nv_bfloat16 g_xhi[TOTAL_ELEMS];
__device__ __align__(128) __nv_bfloat16 g_xlo[TOTAL_ELEMS];
__device__ __align__(128) __nv_bfloat16 g_whi[3342336];
__device__ __align__(128) __nv_bfloat16 g_wlo[3342336];

struct Dims6 { int size[6]; int stride[6]; };

// ---- smem stage layout (BK=32, rows padded 64B->80B for conflict-free ldsm) ----
#define A_HI_OFF 0
#define A_LO_OFF 10240
#define B_HI_OFF 20480
#define B_LO_OFF 40960
#define STAGE_B  61440
#define NSTAGE   3
#define DYN_SMEM (NSTAGE * STAGE_B)   // 184320

__device__ __forceinline__ uint32_t smem_u32(const void* p) {
    uint32_t a;
    asm("{ .reg .u64 t; cvta.to.shared.u64 t, %1; cvt.u32.u64 %0, t; }" : "=r"(a) : "l"(p));
    return a;
}
__device__ __forceinline__ void ldsm4(uint32_t* r, uint32_t a) {
    asm volatile("ldmatrix.sync.aligned.m8n8.x4.shared.b16 {%0,%1,%2,%3}, [%4];"
        : "=r"(r[0]), "=r"(r[1]), "=r"(r[2]), "=r"(r[3]) : "r"(a));
}
__device__ __forceinline__ void mma16816(float* d, const uint32_t* a, const uint32_t* b) {
    asm volatile("mma.sync.aligned.m16n8k16.row.col.f32.bf16.bf16.f32 "
        "{%0,%1,%2,%3}, {%4,%5,%6,%7}, {%8,%9}, {%0,%1,%2,%3};"
        : "+f"(d[0]), "+f"(d[1]), "+f"(d[2]), "+f"(d[3])
        : "r"(a[0]), "r"(a[1]), "r"(a[2]), "r"(a[3]), "r"(b[0]), "r"(b[1]));
}
__device__ __forceinline__ void cpa16(uint32_t s, const void* g) {
    asm volatile("cp.async.cg.shared.global [%0], [%1], 16;" :: "r"(s), "l"(g));
}
#define CPA_COMMIT() asm volatile("cp.async.commit_group;" ::: "memory")
#define CPA_WAIT1()  asm volatile("cp.async.wait_group 1;" ::: "memory")

// ================= prep: X fp32 (original) -> bf16 hi/lo (permuted, c fastest) ==========
__global__ __launch_bounds__(256) void prep_x(const float* __restrict__ X)
{
    __shared__ float ts[64][65];
    const int b = blockIdx.x >> 12, sblk = blockIdx.x & 4095;
    const size_t s0 = (size_t)sblk * 64;
    const int t = threadIdx.x, sl = t & 63, ch = t >> 6;
    const float* xp = X + (size_t)b * 64 * 262144 + s0;
    #pragma unroll
    for (int i = 0; i < 16; i++) {
        const int c = ch + i * 4;
        ts[sl][c] = xp[(size_t)c * 262144 + sl];
    }
    __syncthreads();
    const int srow = t >> 2, sub = t & 3;
    const size_t row = (size_t)b * 262144 + s0 + srow;
    __nv_bfloat16* hp = g_xhi + row * 64 + sub * 16;
    __nv_bfloat16* lp = g_xlo + row * 64 + sub * 16;
    #pragma unroll
    for (int j = 0; j < 16; j++) {
        const float v = ts[srow][sub * 16 + j];
        const __nv_bfloat16 h = __float2bfloat16(v);
        hp[j] = h;
        lp[j] = __float2bfloat16(v - __bfloat162float(h));
    }
}

__global__ __launch_bounds__(256) void prep_w(const float* __restrict__ W, int woff, int n)
{
    const int row = blockIdx.x;
    const float* wp = W + (size_t)row * n;
    __nv_bfloat16* hp = g_whi + woff + (size_t)row * n;
    __nv_bfloat16* lp = g_wlo + woff + (size_t)row * n;
    for (int c = threadIdx.x; c < n; c += 256) {
        const float v = wp[c];
        const __nv_bfloat16 h = __float2bfloat16(v);
        hp[c] = h;
        lp[c] = __float2bfloat16(v - __bfloat162float(h));
    }
}

// ================= GEMM: 128m x 256n tile, BK=32, 512 threads, 3-stage cp.async =========
__global__ __launch_bounds__(512, 1)
void axial_mma(int woff, const float* __restrict__ Bias, Dims6 dims,
               int n, int str_sp, int first)
{
    extern __shared__ __align__(16) char dsm[];
    __shared__ int base_s[128];

    const int tid = threadIdx.x;
    const int lane = tid & 31, wid = tid >> 5;
    const int nb = blockIdx.x, bx = blockIdx.y;
    const int wm = wid & 3, wn = wid >> 2;

    if (tid < 128) {
        int m = bx * 128 + tid;
        int off = 0;
        #pragma unroll
        for (int j = 0; j < 6; j++) { off += (m % dims.size[j]) * dims.stride[j]; m /= dims.size[j]; }
        base_s[tid] = off;
    }
    __syncthreads();

    const uint32_t sb = smem_u32(dsm);

    // ---- per-thread cp.async constants ----
    const int aM   = (tid >> 1) & 127;          // A row within tile
    const int aChk = (tid & 1) * 2;             // chunk pair {0,1} or {2,3}
    const int bRow = tid & 255;                 // B row within tile
    const bool loHalf = (tid >= 256);
    const int aBase = base_s[aM];
    const __nv_bfloat16* aSrc = loHalf ? g_xlo : g_xhi;
    const __nv_bfloat16* bSrc = (loHalf ? g_wlo : g_whi) + woff
                              + (size_t)(nb * 256 + bRow) * n;
    const uint32_t aSm = (loHalf ? A_LO_OFF : A_HI_OFF) + (uint32_t)(aM * 80 + aChk * 16);
    const uint32_t bSm = (loHalf ? B_LO_OFF : B_HI_OFF) + (uint32_t)(bRow * 80);

    auto issue = [&](int ck) {
        const uint32_t st = sb + (uint32_t)((ck % 3) * STAGE_B);
        const char* ga = (const char*)aSrc
            + ((size_t)(aBase + (ck >> 1) * str_sp)) * 128 + (ck & 1) * 64 + aChk * 16;
        cpa16(st + aSm,      ga);
        cpa16(st + aSm + 16, ga + 16);
        const char* gb = (const char*)(bSrc + ck * 32);
        cpa16(st + bSm,      gb);
        cpa16(st + bSm + 16, gb + 16);
        cpa16(st + bSm + 32, gb + 32);
        cpa16(st + bSm + 48, gb + 48);
    };

    // ---- ldsm lane offsets ----
    const uint32_t a_off = (uint32_t)((wm * 32 + (lane & 15)) * 80 + (lane >> 4) * 16);
    const uint32_t b_off = (uint32_t)(B_HI_OFF
        + (wn * 64 + ((lane >> 4) & 1) * 8 + (lane & 7)) * 80 + ((lane >> 3) & 1) * 16);

    float acc[2][8][4];
    #pragma unroll
    for (int i = 0; i < 2; i++)
        #pragma unroll
        for (int j = 0; j < 8; j++)
            #pragma unroll
            for (int q = 0; q < 4; q++) acc[i][j][q] = 0.f;

    const int nk = n >> 5;
    issue(0); CPA_COMMIT();
    issue(1); CPA_COMMIT();

    for (int ck = 0; ck < nk; ck++) {
        CPA_WAIT1();
        __syncthreads();
        if (ck + 2 < nk) issue(ck + 2);
        CPA_COMMIT();

        const uint32_t st = sb + (uint32_t)((ck % 3) * STAGE_B);
        #pragma unroll
        for (int ks = 0; ks < 2; ks++) {
            const uint32_t ko = (uint32_t)(ks * 32);
            uint32_t ah[2][4], al[2][4];
            ldsm4(ah[0], st + a_off + ko);
            ldsm4(ah[1], st + a_off + 1280 + ko);
            ldsm4(al[0], st + A_LO_OFF + a_off + ko);
            ldsm4(al[1], st + A_LO_OFF + a_off + 1280 + ko);
            #pragma unroll
            for (int ntp = 0; ntp < 4; ntp++) {
                uint32_t bh[4], bl[4];
                ldsm4(bh, st + b_off + ntp * 1280 + ko);
                mma16816(acc[0][2*ntp],   ah[0], bh);
                mma16816(acc[0][2*ntp+1], ah[0], bh + 2);
                mma16816(acc[1][2*ntp],   ah[1], bh);
                mma16816(acc[1][2*ntp+1], ah[1], bh + 2);
                mma16816(acc[0][2*ntp],   al[0], bh);
                mma16816(acc[0][2*ntp+1], al[0], bh + 2);
                mma16816(acc[1][2*ntp],   al[1], bh);
                mma16816(acc[1][2*ntp+1], al[1], bh + 2);
                ldsm4(bl, st + 20480 + b_off + ntp * 1280 + ko);
                mma16816(acc[0][2*ntp],   ah[0], bl);
                mma16816(acc[0][2*ntp+1], ah[0], bl + 2);
                mma16816(acc[1][2*ntp],   ah[1], bl);
                mma16816(acc[1][2*ntp+1], ah[1], bl + 2);
            }
        }
    }

    // ---- epilogue: RMW into permuted g_acc (c contiguous -> float2) ----
    {
        const int s_out = nb * 4 + wn;
        const int r0 = lane >> 2, cp = (lane & 3) * 2;
        #pragma unroll
        for (int mt = 0; mt < 2; mt++) {
            const int ml = wm * 32 + mt * 16 + r0;
            const size_t row0 = (size_t)(base_s[ml]     + s_out * str_sp);
            const size_t row1 = (size_t)(base_s[ml + 8] + s_out * str_sp);
            #pragma unroll
            for (int nt = 0; nt < 8; nt++) {
                const int o = nb * 256 + wn * 64 + nt * 8 + cp;
                const int c_out = nt * 8 + cp;
                const float2 bv = __ldg((const float2*)(Bias + o));
                float2* g0 = (float2*)(g_acc + row0 * 64 + c_out);
                float2* g1 = (float2*)(g_acc + row1 * 64 + c_out);
                if (first) {
                    *g0 = make_float2(acc[mt][nt][0] + bv.x, acc[mt][nt][1] + bv.y);
                    *g1 = make_float2(acc[mt][nt][2] + bv.x, acc[mt][nt][3] + bv.y);
                } else {
                    float2 v0 = *g0, v1 = *g1;
                    v0.x += acc[mt][nt][0] + bv.x; v0.y += acc[mt][nt][1] + bv.y;
                    v1.x += acc[mt][nt][2] + bv.x; v1.y += acc[mt][nt][3] + bv.y;
                    *g0 = v0; *g1 = v1;
                }
            }
        }
    }
}

// ============ finalize: permuted g_acc -> leaky + residual -> original-layout out =======
__global__ __launch_bounds__(256) void finalize2(const float* __restrict__ X,
                                                 float* __restrict__ Y)
{
    __shared__ float ts[64][65];
    const int b = blockIdx.x >> 12, sblk = blockIdx.x & 4095;
    const size_t s0 = (size_t)sblk * 64;
    const int t = threadIdx.x, sl = t & 63, ch = t >> 6;
    #pragma unroll
    for (int i = 0; i < 16; i++) {
        const int s = ch + i * 4;
        ts[s][sl] = g_acc[((size_t)b * 262144 + s0 + s) * 64 + sl];
    }
    __syncthreads();
    #pragma unroll
    for (int i = 0; i < 16; i++) {
        const int c = ch + i * 4;
        const size_t oa = ((size_t)(b * 64 + c)) * 262144 + s0 + sl;
        const float a = ts[sl][c];
        Y[oa] = X[oa] + (a > 0.f ? a : 0.01f * a);
    }
}

extern "C" void kernel_launch(void* const* d_in, const int* in_sizes, int n_in,
                              void* d_out, int out_size)
{
    const float* x    = (const float*)d_in[0];
    const float* w_d  = (const float*)d_in[1];
    const float* b_d  = (const float*)d_in[2];
    const float* w_h  = (const float*)d_in[3];
    const float* b_h  = (const float*)d_in[4];
    const float* w_w  = (const float*)d_in[5];
    const float* b_w  = (const float*)d_in[6];
    const float* w_pd = (const float*)d_in[7];
    const float* b_pd = (const float*)d_in[8];
    const float* w_ph = (const float*)d_in[9];
    const float* b_ph = (const float*)d_in[10];
    const float* w_pw = (const float*)d_in[11];
    const float* b_pw = (const float*)d_in[12];

    cudaFuncSetAttribute(axial_mma, cudaFuncAttributeMaxDynamicSharedMemorySize, DYN_SMEM);

    // weight buffer offsets (elements)
    const int OW_D = 0, OW_H = 1048576, OW_W = 2097152;
    const int OW_PD = 3145728, OW_PH = 3211264, OW_PW = 3276800;

    prep_x<<<8192, 256>>>(x);
    prep_w<<<1024, 256>>>(w_d,  OW_D,  1024);
    prep_w<<<1024, 256>>>(w_h,  OW_H,  1024);
    prep_w<<<1024, 256>>>(w_w,  OW_W,  1024);
    prep_w<<<256,  256>>>(w_pd, OW_PD, 256);
    prep_w<<<256,  256>>>(w_ph, OW_PH, 256);
    prep_w<<<256,  256>>>(w_pw, OW_PW, 256);

    // m-dims (sizes, spatial-row strides incl. b=262144), fastest first
    Dims6 dD = {{4,4,4,16,16,2},  {1,4,16,64,1024,262144}};    // axis d (str 16384)
    Dims6 dH = {{4,4,4,16,16,2},  {1,4,16,64,16384,262144}};   // axis h (str 1024)
    Dims6 dW = {{4,4,4,16,16,2},  {1,4,16,1024,16384,262144}}; // axis w (str 64)
    Dims6 dP = {{4,4,16,16,16,2}, {1,4,64,1024,16384,262144}}; // axis p (str 16)
    Dims6 dQ = {{4,4,16,16,16,2}, {1,16,64,1024,16384,262144}};// axis q (str 4)
    Dims6 dR = {{4,4,16,16,16,2}, {4,16,64,1024,16384,262144}};// axis r (str 1)

    // patch ops: M=131072 -> grid (1,1024); image ops: M=32768, N=1024 -> grid (4,256)
    axial_mma<<<dim3(1, 1024), 512, DYN_SMEM>>>(OW_PD, b_pd, dP, 256, 16,    1);
    axial_mma<<<dim3(1, 1024), 512, DYN_SMEM>>>(OW_PH, b_ph, dQ, 256, 4,     0);
    axial_mma<<<dim3(1, 1024), 512, DYN_SMEM>>>(OW_PW, b_pw, dR, 256, 1,     0);
    axial_mma<<<dim3(4, 256),  512, DYN_SMEM>>>(OW_D,  b_d,  dD, 1024, 16384, 0);
    axial_mma<<<dim3(4, 256),  512, DYN_SMEM>>>(OW_H,  b_h,  dH, 1024, 1024,  0);
    axial_mma<<<dim3(4, 256),  512, DYN_SMEM>>>(OW_W,  b_w,  dW, 1024, 64,    0);

    finalize2<<<8192, 256>>>(x, (float*)d_out);
}

// round 5
// speedup vs baseline: 3.0651x; 1.1199x over previous
#include <cuda_runtime.h>
#include <cuda_bf16.h>
#include <cstdint>

#define TOTAL_ELEMS 33554432

__device__ __align__(128) float g_acc[TOTAL_ELEMS];
__device__ __align__(128) __nv_bfloat16 g_xhi[TOTAL_ELEMS];
__device__ __align__(128) __nv_bfloat16 g_xlo[TOTAL_ELEMS];
__device__ __align__(128) __nv_bfloat16 g_whi[3342336];
__device__ __align__(128) __nv_bfloat16 g_wlo[3342336];

struct Dims6 { int size[6]; int stride[6]; };

// stage: A_hi 10240 | A_lo 10240 | B_hi 10240 | B_lo 10240 (128 rows x 80B padded)
#define A_HI_OFF 0
#define A_LO_OFF 10240
#define B_HI_OFF 20480
#define B_LO_OFF 30720
#define STAGE_B  40960
#define DYN_SMEM (2 * STAGE_B)   // 81920 -> 2 CTAs/SM

__device__ __forceinline__ uint32_t smem_u32(const void* p) {
    uint32_t a;
    asm("{ .reg .u64 t; cvta.to.shared.u64 t, %1; cvt.u32.u64 %0, t; }" : "=r"(a) : "l"(p));
    return a;
}
__device__ __forceinline__ void ldsm4(uint32_t* r, uint32_t a) {
    asm volatile("ldmatrix.sync.aligned.m8n8.x4.shared.b16 {%0,%1,%2,%3}, [%4];"
        : "=r"(r[0]), "=r"(r[1]), "=r"(r[2]), "=r"(r[3]) : "r"(a));
}
__device__ __forceinline__ void mma16816(float* d, const uint32_t* a, const uint32_t* b) {
    asm volatile("mma.sync.aligned.m16n8k16.row.col.f32.bf16.bf16.f32 "
        "{%0,%1,%2,%3}, {%4,%5,%6,%7}, {%8,%9}, {%0,%1,%2,%3};"
        : "+f"(d[0]), "+f"(d[1]), "+f"(d[2]), "+f"(d[3])
        : "r"(a[0]), "r"(a[1]), "r"(a[2]), "r"(a[3]), "r"(b[0]), "r"(b[1]));
}
__device__ __forceinline__ void cpa16(uint32_t s, const void* g) {
    asm volatile("cp.async.cg.shared.global [%0], [%1], 16;" :: "r"(s), "l"(g));
}
#define CPA_COMMIT() asm volatile("cp.async.commit_group;" ::: "memory")
#define CPA_WAIT1()  asm volatile("cp.async.wait_group 1;" ::: "memory")
#define CPA_WAIT0()  asm volatile("cp.async.wait_group 0;" ::: "memory")

// ================= prep: X fp32 (original) -> bf16 hi/lo (permuted, c fastest) ==========
__global__ __launch_bounds__(256) void prep_x(const float* __restrict__ X)
{
    __shared__ float ts[64][65];
    const int b = blockIdx.x >> 12, sblk = blockIdx.x & 4095;
    const size_t s0 = (size_t)sblk * 64;
    const int t = threadIdx.x, sl = t & 63, ch = t >> 6;
    const float* xp = X + (size_t)b * 64 * 262144 + s0;
    #pragma unroll
    for (int i = 0; i < 16; i++) {
        const int c = ch + i * 4;
        ts[sl][c] = xp[(size_t)c * 262144 + sl];
    }
    __syncthreads();
    const int srow = t >> 2, sub = t & 3;
    const size_t row = (size_t)b * 262144 + s0 + srow;
    __nv_bfloat16* hp = g_xhi + row * 64 + sub * 16;
    __nv_bfloat16* lp = g_xlo + row * 64 + sub * 16;
    #pragma unroll
    for (int j = 0; j < 16; j++) {
        const float v = ts[srow][sub * 16 + j];
        const __nv_bfloat16 h = __float2bfloat16(v);
        hp[j] = h;
        lp[j] = __float2bfloat16(v - __bfloat162float(h));
    }
}

__global__ __launch_bounds__(256) void prep_w(const float* __restrict__ W, int woff, int n)
{
    const int row = blockIdx.x;
    const float* wp = W + (size_t)row * n;
    __nv_bfloat16* hp = g_whi + woff + (size_t)row * n;
    __nv_bfloat16* lp = g_wlo + woff + (size_t)row * n;
    for (int c = threadIdx.x; c < n; c += 256) {
        const float v = wp[c];
        const __nv_bfloat16 h = __float2bfloat16(v);
        hp[c] = h;
        lp[c] = __float2bfloat16(v - __bfloat162float(h));
    }
}

// ========= GEMM: 128m x 128n tile, BK=32, 256 threads, 2-stage cp.async, 2 CTA/SM =======
__global__ __launch_bounds__(256, 2)
void axial_mma(int woff, const float* __restrict__ Bias, Dims6 dims,
               int n, int str_sp, int first)
{
    extern __shared__ __align__(16) char dsm[];
    __shared__ int base_s[128];

    const int tid = threadIdx.x;
    const int lane = tid & 31, wid = tid >> 5;
    const int nb = blockIdx.x, bx = blockIdx.y;
    const int wm = wid & 3, wn = wid >> 2;     // warp tile: rows wm*32(+32), cols wn*64(+64)

    if (tid < 128) {
        int m = bx * 128 + tid;
        int off = 0;
        #pragma unroll
        for (int j = 0; j < 6; j++) { off += (m % dims.size[j]) * dims.stride[j]; m /= dims.size[j]; }
        base_s[tid] = off;
    }
    __syncthreads();

    const uint32_t sb = smem_u32(dsm);

    // ---- cp.async mapping: thread t -> row t>>1, two 16B chunks at c16=(t&1)*2 ----
    const int row = tid >> 1;
    const int c16 = (tid & 1) * 2;
    const int aBase = base_s[row];
    const char* aHi = (const char*)g_xhi;
    const char* aLo = (const char*)g_xlo;
    const char* bHi = (const char*)(g_whi + woff) + ((size_t)(nb * 128 + row)) * n * 2 + c16 * 16;
    const char* bLo = (const char*)(g_wlo + woff) + ((size_t)(nb * 128 + row)) * n * 2 + c16 * 16;
    const uint32_t aSm = (uint32_t)(row * 80 + c16 * 16);
    const uint32_t bSm = (uint32_t)(row * 80 + c16 * 16);

    auto issue = [&](int ck) {
        const uint32_t st = sb + (uint32_t)((ck & 1) * STAGE_B);
        const size_t aoff = ((size_t)(aBase + (ck >> 1) * str_sp)) * 128
                          + (ck & 1 ? 64 : 0) + c16 * 16;
        cpa16(st + A_HI_OFF + aSm,      aHi + aoff);
        cpa16(st + A_HI_OFF + aSm + 16, aHi + aoff + 16);
        cpa16(st + A_LO_OFF + aSm,      aLo + aoff);
        cpa16(st + A_LO_OFF + aSm + 16, aLo + aoff + 16);
        const size_t boff = (size_t)ck * 64;
        cpa16(st + B_HI_OFF + bSm,      bHi + boff);
        cpa16(st + B_HI_OFF + bSm + 16, bHi + boff + 16);
        cpa16(st + B_LO_OFF + bSm,      bLo + boff);
        cpa16(st + B_LO_OFF + bSm + 16, bLo + boff + 16);
    };

    // ---- ldsm lane offsets ----
    const uint32_t a_lm = (uint32_t)((wm * 32 + (lane & 15)) * 80 + (lane >> 4) * 16);
    const uint32_t b_lm = (uint32_t)((wn * 64 + ((lane >> 4) & 1) * 8 + (lane & 7)) * 80
                                     + ((lane >> 3) & 1) * 16);

    float acc[2][8][4];
    #pragma unroll
    for (int i = 0; i < 2; i++)
        #pragma unroll
        for (int j = 0; j < 8; j++)
            #pragma unroll
            for (int q = 0; q < 4; q++) acc[i][j][q] = 0.f;

    const int nk = n >> 5;
    issue(0); CPA_COMMIT();

    for (int ck = 0; ck < nk; ck++) {
        if (ck + 1 < nk) { issue(ck + 1); CPA_COMMIT(); CPA_WAIT1(); }
        else             { CPA_WAIT0(); }
        __syncthreads();

        const uint32_t st = sb + (uint32_t)((ck & 1) * STAGE_B);
        #pragma unroll
        for (int ks = 0; ks < 2; ks++) {
            const uint32_t ko = (uint32_t)(ks * 32);
            uint32_t ah[2][4], al[2][4], br[4];
            ldsm4(ah[0], st + A_HI_OFF + a_lm + ko);
            ldsm4(ah[1], st + A_HI_OFF + a_lm + 1280 + ko);
            ldsm4(al[0], st + A_LO_OFF + a_lm + ko);
            ldsm4(al[1], st + A_LO_OFF + a_lm + 1280 + ko);
            #pragma unroll
            for (int ntp = 0; ntp < 4; ntp++) {
                ldsm4(br, st + B_HI_OFF + b_lm + ntp * 1280 + ko);
                mma16816(acc[0][2*ntp],   ah[0], br);
                mma16816(acc[0][2*ntp+1], ah[0], br + 2);
                mma16816(acc[1][2*ntp],   ah[1], br);
                mma16816(acc[1][2*ntp+1], ah[1], br + 2);
                mma16816(acc[0][2*ntp],   al[0], br);
                mma16816(acc[0][2*ntp+1], al[0], br + 2);
                mma16816(acc[1][2*ntp],   al[1], br);
                mma16816(acc[1][2*ntp+1], al[1], br + 2);
                ldsm4(br, st + B_LO_OFF + b_lm + ntp * 1280 + ko);
                mma16816(acc[0][2*ntp],   ah[0], br);
                mma16816(acc[0][2*ntp+1], ah[0], br + 2);
                mma16816(acc[1][2*ntp],   ah[1], br);
                mma16816(acc[1][2*ntp+1], ah[1], br + 2);
            }
        }
        __syncthreads();
    }

    // ---- epilogue: RMW into permuted g_acc (c contiguous -> float2) ----
    {
        const int s_out = nb * 2 + wn;
        const int r0 = lane >> 2, cp = (lane & 3) * 2;
        #pragma unroll
        for (int mt = 0; mt < 2; mt++) {
            const int ml = wm * 32 + mt * 16 + r0;
            const size_t row0 = (size_t)(base_s[ml]     + s_out * str_sp);
            const size_t row1 = (size_t)(base_s[ml + 8] + s_out * str_sp);
            #pragma unroll
            for (int nt = 0; nt < 8; nt++) {
                const int o = nb * 128 + wn * 64 + nt * 8 + cp;
                const int c_out = nt * 8 + cp;
                const float2 bv = __ldg((const float2*)(Bias + o));
                float2* g0 = (float2*)(g_acc + row0 * 64 + c_out);
                float2* g1 = (float2*)(g_acc + row1 * 64 + c_out);
                if (first) {
                    *g0 = make_float2(acc[mt][nt][0] + bv.x, acc[mt][nt][1] + bv.y);
                    *g1 = make_float2(acc[mt][nt][2] + bv.x, acc[mt][nt][3] + bv.y);
                } else {
                    float2 v0 = *g0, v1 = *g1;
                    v0.x += acc[mt][nt][0] + bv.x; v0.y += acc[mt][nt][1] + bv.y;
                    v1.x += acc[mt][nt][2] + bv.x; v1.y += acc[mt][nt][3] + bv.y;
                    *g0 = v0; *g1 = v1;
                }
            }
        }
    }
}

// ============ finalize: permuted g_acc -> leaky + residual -> original-layout out =======
__global__ __launch_bounds__(256) void finalize2(const float* __restrict__ X,
                                                 float* __restrict__ Y)
{
    __shared__ float ts[64][65];
    const int b = blockIdx.x >> 12, sblk = blockIdx.x & 4095;
    const size_t s0 = (size_t)sblk * 64;
    const int t = threadIdx.x, sl = t & 63, ch = t >> 6;
    #pragma unroll
    for (int i = 0; i < 16; i++) {
        const int s = ch + i * 4;
        ts[s][sl] = g_acc[((size_t)b * 262144 + s0 + s) * 64 + sl];
    }
    __syncthreads();
    #pragma unroll
    for (int i = 0; i < 16; i++) {
        const int c = ch + i * 4;
        const size_t oa = ((size_t)(b * 64 + c)) * 262144 + s0 + sl;
        const float a = ts[sl][c];
        Y[oa] = X[oa] + (a > 0.f ? a : 0.01f * a);
    }
}

extern "C" void kernel_launch(void* const* d_in, const int* in_sizes, int n_in,
                              void* d_out, int out_size)
{
    const float* x    = (const float*)d_in[0];
    const float* w_d  = (const float*)d_in[1];
    const float* b_d  = (const float*)d_in[2];
    const float* w_h  = (const float*)d_in[3];
    const float* b_h  = (const float*)d_in[4];
    const float* w_w  = (const float*)d_in[5];
    const float* b_w  = (const float*)d_in[6];
    const float* w_pd = (const float*)d_in[7];
    const float* b_pd = (const float*)d_in[8];
    const float* w_ph = (const float*)d_in[9];
    const float* b_ph = (const float*)d_in[10];
    const float* w_pw = (const float*)d_in[11];
    const float* b_pw = (const float*)d_in[12];

    cudaFuncSetAttribute(axial_mma, cudaFuncAttributeMaxDynamicSharedMemorySize, DYN_SMEM);

    const int OW_D = 0, OW_H = 1048576, OW_W = 2097152;
    const int OW_PD = 3145728, OW_PH = 3211264, OW_PW = 3276800;

    prep_x<<<8192, 256>>>(x);
    prep_w<<<1024, 256>>>(w_d,  OW_D,  1024);
    prep_w<<<1024, 256>>>(w_h,  OW_H,  1024);
    prep_w<<<1024, 256>>>(w_w,  OW_W,  1024);
    prep_w<<<256,  256>>>(w_pd, OW_PD, 256);
    prep_w<<<256,  256>>>(w_ph, OW_PH, 256);
    prep_w<<<256,  256>>>(w_pw, OW_PW, 256);

    // m-dims (sizes, spatial-row strides incl. b=262144), fastest first
    Dims6 dD = {{4,4,4,16,16,2},  {1,4,16,64,1024,262144}};    // axis d (str 16384)
    Dims6 dH = {{4,4,4,16,16,2},  {1,4,16,64,16384,262144}};   // axis h (str 1024)
    Dims6 dW = {{4,4,4,16,16,2},  {1,4,16,1024,16384,262144}}; // axis w (str 64)
    Dims6 dP = {{4,4,16,16,16,2}, {1,4,64,1024,16384,262144}}; // axis p (str 16)
    Dims6 dQ = {{4,4,16,16,16,2}, {1,16,64,1024,16384,262144}};// axis q (str 4)
    Dims6 dR = {{4,4,16,16,16,2}, {4,16,64,1024,16384,262144}};// axis r (str 1)

    // patch ops: N=256 -> grid (2,1024); image ops: N=1024 -> grid (8,256)
    axial_mma<<<dim3(2, 1024), 256, DYN_SMEM>>>(OW_PD, b_pd, dP, 256, 16,    1);
    axial_mma<<<dim3(2, 1024), 256, DYN_SMEM>>>(OW_PH, b_ph, dQ, 256, 4,     0);
    axial_mma<<<dim3(2, 1024), 256, DYN_SMEM>>>(OW_PW, b_pw, dR, 256, 1,     0);
    axial_mma<<<dim3(8, 256),  256, DYN_SMEM>>>(OW_D,  b_d,  dD, 1024, 16384, 0);
    axial_mma<<<dim3(8, 256),  256, DYN_SMEM>>>(OW_H,  b_h,  dH, 1024, 1024,  0);
    axial_mma<<<dim3(8, 256),  256, DYN_SMEM>>>(OW_W,  b_w,  dW, 1024, 64,    0);

    finalize2<<<8192, 256>>>(x, (float*)d_out);
}

// round 6
// speedup vs baseline: 4.2204x; 1.3769x over previous
#include <cuda_runtime.h>
#include <cuda_fp16.h>
#include <cstdint>

#define TOTAL_ELEMS 33554432

__device__ __align__(128) float g_acc[TOTAL_ELEMS];
__device__ __align__(128) __half g_xhi[TOTAL_ELEMS];
__device__ __align__(128) __half g_xlo[TOTAL_ELEMS];
__device__ __align__(128) __half g_whi[3342336];

struct Dims6 { int size[6]; int stride[6]; };

// stage: A_hi 10240 | A_lo 10240 | B_hi 10240  (128 rows x 80B padded)
#define A_HI_OFF 0
#define A_LO_OFF 10240
#define B_HI_OFF 20480
#define STAGE_B  30720
#define NSTAGE   3
#define DYN_SMEM (NSTAGE * STAGE_B)   // 92160; 2 CTAs/SM = 184320 <= 227KB

__device__ __forceinline__ uint32_t smem_u32(const void* p) {
    uint32_t a;
    asm("{ .reg .u64 t; cvta.to.shared.u64 t, %1; cvt.u32.u64 %0, t; }" : "=r"(a) : "l"(p));
    return a;
}
__device__ __forceinline__ void ldsm4(uint32_t* r, uint32_t a) {
    asm volatile("ldmatrix.sync.aligned.m8n8.x4.shared.b16 {%0,%1,%2,%3}, [%4];"
        : "=r"(r[0]), "=r"(r[1]), "=r"(r[2]), "=r"(r[3]) : "r"(a));
}
__device__ __forceinline__ void mma16816(float* d, const uint32_t* a, const uint32_t* b) {
    asm volatile("mma.sync.aligned.m16n8k16.row.col.f32.f16.f16.f32 "
        "{%0,%1,%2,%3}, {%4,%5,%6,%7}, {%8,%9}, {%0,%1,%2,%3};"
        : "+f"(d[0]), "+f"(d[1]), "+f"(d[2]), "+f"(d[3])
        : "r"(a[0]), "r"(a[1]), "r"(a[2]), "r"(a[3]), "r"(b[0]), "r"(b[1]));
}
__device__ __forceinline__ void cpa16(uint32_t s, const void* g) {
    asm volatile("cp.async.cg.shared.global [%0], [%1], 16;" :: "r"(s), "l"(g));
}
#define CPA_COMMIT() asm volatile("cp.async.commit_group;" ::: "memory")
#define CPA_WAIT1()  asm volatile("cp.async.wait_group 1;" ::: "memory")
#define CPA_WAIT0()  asm volatile("cp.async.wait_group 0;" ::: "memory")

// ================= prep: X fp32 (original) -> fp16 hi/lo (permuted, c fastest) ==========
__global__ __launch_bounds__(256) void prep_x(const float* __restrict__ X)
{
    __shared__ float ts[64][65];
    const int b = blockIdx.x >> 12, sblk = blockIdx.x & 4095;
    const size_t s0 = (size_t)sblk * 64;
    const int t = threadIdx.x, sl = t & 63, ch = t >> 6;
    const float* xp = X + (size_t)b * 64 * 262144 + s0;
    #pragma unroll
    for (int i = 0; i < 16; i++) {
        const int c = ch + i * 4;
        ts[sl][c] = xp[(size_t)c * 262144 + sl];
    }
    __syncthreads();
    const int srow = t >> 2, sub = t & 3;
    const size_t row = (size_t)b * 262144 + s0 + srow;
    __half* hp = g_xhi + row * 64 + sub * 16;
    __half* lp = g_xlo + row * 64 + sub * 16;
    #pragma unroll
    for (int j = 0; j < 16; j++) {
        const float v = ts[srow][sub * 16 + j];
        const __half h = __float2half(v);
        hp[j] = h;
        lp[j] = __float2half(v - __half2float(h));
    }
}

__global__ __launch_bounds__(256) void prep_w(const float* __restrict__ W, int woff, int n)
{
    const int row = blockIdx.x;
    const float* wp = W + (size_t)row * n;
    __half* hp = g_whi + woff + (size_t)row * n;
    for (int c = threadIdx.x; c < n; c += 256)
        hp[c] = __float2half(wp[c]);
}

// ==== GEMM: 128m x 128n tile, BK=32, 256 threads, 3-stage cp.async, 2 CTA/SM ====
__global__ __launch_bounds__(256, 2)
void axial_mma(int woff, const float* __restrict__ Bias, Dims6 dims,
               int n, int str_sp, int first)
{
    extern __shared__ __align__(16) char dsm[];
    __shared__ int base_s[128];

    const int tid = threadIdx.x;
    const int lane = tid & 31, wid = tid >> 5;
    const int nb = blockIdx.x, bx = blockIdx.y;
    const int wm = wid & 3, wn = wid >> 2;     // warp tile: 32m x 64n

    if (tid < 128) {
        int m = bx * 128 + tid;
        int off = 0;
        #pragma unroll
        for (int j = 0; j < 6; j++) { off += (m % dims.size[j]) * dims.stride[j]; m /= dims.size[j]; }
        base_s[tid] = off;
    }
    __syncthreads();

    const uint32_t sb = smem_u32(dsm);

    // ---- cp.async mapping: thread t -> row t>>1, two 16B chunks at c16=(t&1)*2 ----
    const int row = tid >> 1;
    const int c16 = (tid & 1) * 2;
    const int aBase = base_s[row];
    const char* aHi = (const char*)g_xhi;
    const char* aLo = (const char*)g_xlo;
    const char* bHi = (const char*)(g_whi + woff) + ((size_t)(nb * 128 + row)) * n * 2 + c16 * 16;
    const uint32_t rSm = (uint32_t)(row * 80 + c16 * 16);

    auto issue = [&](int ck) {
        const uint32_t st = sb + (uint32_t)((ck % 3) * STAGE_B);
        const size_t aoff = ((size_t)(aBase + (ck >> 1) * str_sp)) * 128
                          + (ck & 1 ? 64 : 0) + c16 * 16;
        cpa16(st + A_HI_OFF + rSm,      aHi + aoff);
        cpa16(st + A_HI_OFF + rSm + 16, aHi + aoff + 16);
        cpa16(st + A_LO_OFF + rSm,      aLo + aoff);
        cpa16(st + A_LO_OFF + rSm + 16, aLo + aoff + 16);
        const size_t boff = (size_t)ck * 64;
        cpa16(st + B_HI_OFF + rSm,      bHi + boff);
        cpa16(st + B_HI_OFF + rSm + 16, bHi + boff + 16);
    };

    // ---- ldsm lane offsets ----
    const uint32_t a_lm = (uint32_t)((wm * 32 + (lane & 15)) * 80 + (lane >> 4) * 16);
    const uint32_t b_lm = (uint32_t)((wn * 64 + ((lane >> 4) & 1) * 8 + (lane & 7)) * 80
                                     + ((lane >> 3) & 1) * 16);

    float acc[2][8][4];
    #pragma unroll
    for (int i = 0; i < 2; i++)
        #pragma unroll
        for (int j = 0; j < 8; j++)
            #pragma unroll
            for (int q = 0; q < 4; q++) acc[i][j][q] = 0.f;

    const int nk = n >> 5;
    issue(0); CPA_COMMIT();
    issue(1); CPA_COMMIT();

    for (int ck = 0; ck < nk; ck++) {
        if (ck + 1 < nk) CPA_WAIT1(); else CPA_WAIT0();
        __syncthreads();
        if (ck + 2 < nk) { issue(ck + 2); CPA_COMMIT(); }

        const uint32_t st = sb + (uint32_t)((ck % 3) * STAGE_B);
        #pragma unroll
        for (int ks = 0; ks < 2; ks++) {
            const uint32_t ko = (uint32_t)(ks * 32);
            uint32_t ah[2][4], al[2][4], br[4];
            ldsm4(ah[0], st + A_HI_OFF + a_lm + ko);
            ldsm4(ah[1], st + A_HI_OFF + a_lm + 1280 + ko);
            ldsm4(al[0], st + A_LO_OFF + a_lm + ko);
            ldsm4(al[1], st + A_LO_OFF + a_lm + 1280 + ko);
            #pragma unroll
            for (int ntp = 0; ntp < 4; ntp++) {
                ldsm4(br, st + B_HI_OFF + b_lm + ntp * 1280 + ko);
                mma16816(acc[0][2*ntp],   ah[0], br);
                mma16816(acc[0][2*ntp+1], ah[0], br + 2);
                mma16816(acc[1][2*ntp],   ah[1], br);
                mma16816(acc[1][2*ntp+1], ah[1], br + 2);
                mma16816(acc[0][2*ntp],   al[0], br);
                mma16816(acc[0][2*ntp+1], al[0], br + 2);
                mma16816(acc[1][2*ntp],   al[1], br);
                mma16816(acc[1][2*ntp+1], al[1], br + 2);
            }
        }
    }

    // ---- epilogue: RMW into permuted g_acc (c contiguous -> float2) ----
    {
        const int s_out = nb * 2 + wn;
        const int r0 = lane >> 2, cp = (lane & 3) * 2;
        #pragma unroll
        for (int mt = 0; mt < 2; mt++) {
            const int ml = wm * 32 + mt * 16 + r0;
            const size_t row0 = (size_t)(base_s[ml]     + s_out * str_sp);
            const size_t row1 = (size_t)(base_s[ml + 8] + s_out * str_sp);
            #pragma unroll
            for (int nt = 0; nt < 8; nt++) {
                const int o = nb * 128 + wn * 64 + nt * 8 + cp;
                const int c_out = nt * 8 + cp;
                const float2 bv = __ldg((const float2*)(Bias + o));
                float2* g0 = (float2*)(g_acc + row0 * 64 + c_out);
                float2* g1 = (float2*)(g_acc + row1 * 64 + c_out);
                if (first) {
                    *g0 = make_float2(acc[mt][nt][0] + bv.x, acc[mt][nt][1] + bv.y);
                    *g1 = make_float2(acc[mt][nt][2] + bv.x, acc[mt][nt][3] + bv.y);
                } else {
                    float2 v0 = *g0, v1 = *g1;
                    v0.x += acc[mt][nt][0] + bv.x; v0.y += acc[mt][nt][1] + bv.y;
                    v1.x += acc[mt][nt][2] + bv.x; v1.y += acc[mt][nt][3] + bv.y;
                    *g0 = v0; *g1 = v1;
                }
            }
        }
    }
}

// ============ finalize: permuted g_acc -> leaky + residual -> original-layout out =======
__global__ __launch_bounds__(256) void finalize2(const float* __restrict__ X,
                                                 float* __restrict__ Y)
{
    __shared__ float ts[64][65];
    const int b = blockIdx.x >> 12, sblk = blockIdx.x & 4095;
    const size_t s0 = (size_t)sblk * 64;
    const int t = threadIdx.x, sl = t & 63, ch = t >> 6;
    #pragma unroll
    for (int i = 0; i < 16; i++) {
        const int s = ch + i * 4;
        ts[s][sl] = g_acc[((size_t)b * 262144 + s0 + s) * 64 + sl];
    }
    __syncthreads();
    #pragma unroll
    for (int i = 0; i < 16; i++) {
        const int c = ch + i * 4;
        const size_t oa = ((size_t)(b * 64 + c)) * 262144 + s0 + sl;
        const float a = ts[sl][c];
        Y[oa] = X[oa] + (a > 0.f ? a : 0.01f * a);
    }
}

extern "C" void kernel_launch(void* const* d_in, const int* in_sizes, int n_in,
                              void* d_out, int out_size)
{
    const float* x    = (const float*)d_in[0];
    const float* w_d  = (const float*)d_in[1];
    const float* b_d  = (const float*)d_in[2];
    const float* w_h  = (const float*)d_in[3];
    const float* b_h  = (const float*)d_in[4];
    const float* w_w  = (const float*)d_in[5];
    const float* b_w  = (const float*)d_in[6];
    const float* w_pd = (const float*)d_in[7];
    const float* b_pd = (const float*)d_in[8];
    const float* w_ph = (const float*)d_in[9];
    const float* b_ph = (const float*)d_in[10];
    const float* w_pw = (const float*)d_in[11];
    const float* b_pw = (const float*)d_in[12];

    cudaFuncSetAttribute(axial_mma, cudaFuncAttributeMaxDynamicSharedMemorySize, DYN_SMEM);

    const int OW_D = 0, OW_H = 1048576, OW_W = 2097152;
    const int OW_PD = 3145728, OW_PH = 3211264, OW_PW = 3276800;

    prep_x<<<8192, 256>>>(x);
    prep_w<<<1024, 256>>>(w_d,  OW_D,  1024);
    prep_w<<<1024, 256>>>(w_h,  OW_H,  1024);
    prep_w<<<1024, 256>>>(w_w,  OW_W,  1024);
    prep_w<<<256,  256>>>(w_pd, OW_PD, 256);
    prep_w<<<256,  256>>>(w_ph, OW_PH, 256);
    prep_w<<<256,  256>>>(w_pw, OW_PW, 256);

    // m-dims (sizes, spatial-row strides incl. b=262144), fastest first
    Dims6 dD = {{4,4,4,16,16,2},  {1,4,16,64,1024,262144}};    // axis d (str 16384)
    Dims6 dH = {{4,4,4,16,16,2},  {1,4,16,64,16384,262144}};   // axis h (str 1024)
    Dims6 dW = {{4,4,4,16,16,2},  {1,4,16,1024,16384,262144}}; // axis w (str 64)
    Dims6 dP = {{4,4,16,16,16,2}, {1,4,64,1024,16384,262144}}; // axis p (str 16)
    Dims6 dQ = {{4,4,16,16,16,2}, {1,16,64,1024,16384,262144}};// axis q (str 4)
    Dims6 dR = {{4,4,16,16,16,2}, {4,16,64,1024,16384,262144}};// axis r (str 1)

    // patch ops: N=256 -> grid (2,1024); image ops: N=1024 -> grid (8,256)
    axial_mma<<<dim3(2, 1024), 256, DYN_SMEM>>>(OW_PD, b_pd, dP, 256, 16,    1);
    axial_mma<<<dim3(2, 1024), 256, DYN_SMEM>>>(OW_PH, b_ph, dQ, 256, 4,     0);
    axial_mma<<<dim3(2, 1024), 256, DYN_SMEM>>>(OW_PW, b_pw, dR, 256, 1,     0);
    axial_mma<<<dim3(8, 256),  256, DYN_SMEM>>>(OW_D,  b_d,  dD, 1024, 16384, 0);
    axial_mma<<<dim3(8, 256),  256, DYN_SMEM>>>(OW_H,  b_h,  dH, 1024, 1024,  0);
    axial_mma<<<dim3(8, 256),  256, DYN_SMEM>>>(OW_W,  b_w,  dW, 1024, 64,    0);

    finalize2<<<8192, 256>>>(x, (float*)d_out);
}

// round 7
// speedup vs baseline: 5.8520x; 1.3866x over previous
#include <cuda_runtime.h>
#include <cuda_fp16.h>
#include <cstdint>

#define TOTAL_ELEMS 33554432

__device__ __align__(128) float g_acc[TOTAL_ELEMS];
__device__ __align__(128) __half g_xhi[TOTAL_ELEMS];
__device__ __align__(128) __half g_whi[3342336];

struct Dims6 { int size[6]; int stride[6]; };

// stage: A 10240 | B 10240  (128 rows x 80B padded)
#define A_OFF 0
#define B_OFF 10240
#define STAGE_B  20480
#define NSTAGE   4
#define DYN_SMEM (NSTAGE * STAGE_B)   // 81920; 2 CTAs/SM = 163840 <= 227KB

__device__ __forceinline__ uint32_t smem_u32(const void* p) {
    uint32_t a;
    asm("{ .reg .u64 t; cvta.to.shared.u64 t, %1; cvt.u32.u64 %0, t; }" : "=r"(a) : "l"(p));
    return a;
}
__device__ __forceinline__ void ldsm4(uint32_t* r, uint32_t a) {
    asm volatile("ldmatrix.sync.aligned.m8n8.x4.shared.b16 {%0,%1,%2,%3}, [%4];"
        : "=r"(r[0]), "=r"(r[1]), "=r"(r[2]), "=r"(r[3]) : "r"(a));
}
__device__ __forceinline__ void mma16816(float* d, const uint32_t* a, const uint32_t* b) {
    asm volatile("mma.sync.aligned.m16n8k16.row.col.f32.f16.f16.f32 "
        "{%0,%1,%2,%3}, {%4,%5,%6,%7}, {%8,%9}, {%0,%1,%2,%3};"
        : "+f"(d[0]), "+f"(d[1]), "+f"(d[2]), "+f"(d[3])
        : "r"(a[0]), "r"(a[1]), "r"(a[2]), "r"(a[3]), "r"(b[0]), "r"(b[1]));
}
__device__ __forceinline__ void cpa16(uint32_t s, const void* g) {
    asm volatile("cp.async.cg.shared.global [%0], [%1], 16;" :: "r"(s), "l"(g));
}
#define CPA_COMMIT() asm volatile("cp.async.commit_group;" ::: "memory")
#define CPA_WAITG(k) asm volatile("cp.async.wait_group %0;" :: "n"(k) : "memory")

// ================= prep: X fp32 (original) -> fp16 (permuted, c fastest) ==========
__global__ __launch_bounds__(256) void prep_x(const float* __restrict__ X)
{
    __shared__ float ts[64][65];
    const int b = blockIdx.x >> 12, sblk = blockIdx.x & 4095;
    const size_t s0 = (size_t)sblk * 64;
    const int t = threadIdx.x, sl = t & 63, ch = t >> 6;
    const float* xp = X + (size_t)b * 64 * 262144 + s0;
    #pragma unroll
    for (int i = 0; i < 16; i++) {
        const int c = ch + i * 4;
        ts[sl][c] = xp[(size_t)c * 262144 + sl];
    }
    __syncthreads();
    const int srow = t >> 2, sub = t & 3;
    const size_t row = (size_t)b * 262144 + s0 + srow;
    __half* hp = g_xhi + row * 64 + sub * 16;
    #pragma unroll
    for (int j = 0; j < 16; j++)
        hp[j] = __float2half(ts[srow][sub * 16 + j]);
}

__global__ __launch_bounds__(256) void prep_w(const float* __restrict__ W, int woff, int n)
{
    const int row = blockIdx.x;
    const float* wp = W + (size_t)row * n;
    __half* hp = g_whi + woff + (size_t)row * n;
    for (int c = threadIdx.x; c < n; c += 256)
        hp[c] = __float2half(wp[c]);
}

// ==== GEMM: 128m x 128n tile, BK=32, 256 threads, 4-stage cp.async, 2 CTA/SM ====
__global__ __launch_bounds__(256, 2)
void axial_mma(int woff, const float* __restrict__ Bias, Dims6 dims,
               int n, int str_sp, int first)
{
    extern __shared__ __align__(16) char dsm[];
    __shared__ int base_s[128];

    const int tid = threadIdx.x;
    const int lane = tid & 31, wid = tid >> 5;
    const int nb = blockIdx.x, bx = blockIdx.y;
    const int wm = wid & 3, wn = wid >> 2;     // warp tile: 32m x 64n

    if (tid < 128) {
        int m = bx * 128 + tid;
        int off = 0;
        #pragma unroll
        for (int j = 0; j < 6; j++) { off += (m % dims.size[j]) * dims.stride[j]; m /= dims.size[j]; }
        base_s[tid] = off;
    }
    __syncthreads();

    const uint32_t sb = smem_u32(dsm);

    // ---- cp.async mapping: thread t -> row t>>1, two 16B chunks at c16=(t&1)*2 ----
    const int row = tid >> 1;
    const int c16 = (tid & 1) * 2;
    const int aBase = base_s[row];
    const char* aHi = (const char*)g_xhi;
    const char* bHi = (const char*)(g_whi + woff) + ((size_t)(nb * 128 + row)) * n * 2 + c16 * 16;
    const uint32_t rSm = (uint32_t)(row * 80 + c16 * 16);

    auto issue = [&](int ck) {
        const uint32_t st = sb + (uint32_t)((ck & 3) * STAGE_B);
        const size_t aoff = ((size_t)(aBase + (ck >> 1) * str_sp)) * 128
                          + (ck & 1 ? 64 : 0) + c16 * 16;
        cpa16(st + A_OFF + rSm,      aHi + aoff);
        cpa16(st + A_OFF + rSm + 16, aHi + aoff + 16);
        const size_t boff = (size_t)ck * 64;
        cpa16(st + B_OFF + rSm,      bHi + boff);
        cpa16(st + B_OFF + rSm + 16, bHi + boff + 16);
    };

    // ---- ldsm lane offsets ----
    const uint32_t a_lm = (uint32_t)((wm * 32 + (lane & 15)) * 80 + (lane >> 4) * 16);
    const uint32_t b_lm = (uint32_t)((wn * 64 + ((lane >> 4) & 1) * 8 + (lane & 7)) * 80
                                     + ((lane >> 3) & 1) * 16);

    float acc[2][8][4];
    #pragma unroll
    for (int i = 0; i < 2; i++)
        #pragma unroll
        for (int j = 0; j < 8; j++)
            #pragma unroll
            for (int q = 0; q < 4; q++) acc[i][j][q] = 0.f;

    const int nk = n >> 5;
    issue(0); CPA_COMMIT();
    issue(1); CPA_COMMIT();
    issue(2); CPA_COMMIT();

    for (int ck = 0; ck < nk; ck++) {
        if (ck + 1 < nk) CPA_WAITG(2); else CPA_WAITG(0);
        __syncthreads();
        if (ck + 3 < nk) { issue(ck + 3); CPA_COMMIT(); }

        const uint32_t st = sb + (uint32_t)((ck & 3) * STAGE_B);
        #pragma unroll
        for (int ks = 0; ks < 2; ks++) {
            const uint32_t ko = (uint32_t)(ks * 32);
            uint32_t ah[2][4], br[4];
            ldsm4(ah[0], st + A_OFF + a_lm + ko);
            ldsm4(ah[1], st + A_OFF + a_lm + 1280 + ko);
            #pragma unroll
            for (int ntp = 0; ntp < 4; ntp++) {
                ldsm4(br, st + B_OFF + b_lm + ntp * 1280 + ko);
                mma16816(acc[0][2*ntp],   ah[0], br);
                mma16816(acc[0][2*ntp+1], ah[0], br + 2);
                mma16816(acc[1][2*ntp],   ah[1], br);
                mma16816(acc[1][2*ntp+1], ah[1], br + 2);
            }
        }
        __syncthreads();
    }

    // ---- epilogue: RMW into permuted g_acc (c contiguous -> float2) ----
    {
        const int s_out = nb * 2 + wn;
        const int r0 = lane >> 2, cp = (lane & 3) * 2;
        #pragma unroll
        for (int mt = 0; mt < 2; mt++) {
            const int ml = wm * 32 + mt * 16 + r0;
            const size_t row0 = (size_t)(base_s[ml]     + s_out * str_sp);
            const size_t row1 = (size_t)(base_s[ml + 8] + s_out * str_sp);
            #pragma unroll
            for (int nt = 0; nt < 8; nt++) {
                const int o = nb * 128 + wn * 64 + nt * 8 + cp;
                const int c_out = nt * 8 + cp;
                const float2 bv = __ldg((const float2*)(Bias + o));
                float2* g0 = (float2*)(g_acc + row0 * 64 + c_out);
                float2* g1 = (float2*)(g_acc + row1 * 64 + c_out);
                if (first) {
                    *g0 = make_float2(acc[mt][nt][0] + bv.x, acc[mt][nt][1] + bv.y);
                    *g1 = make_float2(acc[mt][nt][2] + bv.x, acc[mt][nt][3] + bv.y);
                } else {
                    float2 v0 = *g0, v1 = *g1;
                    v0.x += acc[mt][nt][0] + bv.x; v0.y += acc[mt][nt][1] + bv.y;
                    v1.x += acc[mt][nt][2] + bv.x; v1.y += acc[mt][nt][3] + bv.y;
                    *g0 = v0; *g1 = v1;
                }
            }
        }
    }
}

// ============ finalize: permuted g_acc -> leaky + residual -> original-layout out =======
__global__ __launch_bounds__(256) void finalize2(const float* __restrict__ X,
                                                 float* __restrict__ Y)
{
    __shared__ float ts[64][65];
    const int b = blockIdx.x >> 12, sblk = blockIdx.x & 4095;
    const size_t s0 = (size_t)sblk * 64;
    const int t = threadIdx.x, sl = t & 63, ch = t >> 6;
    #pragma unroll
    for (int i = 0; i < 16; i++) {
        const int s = ch + i * 4;
        ts[s][sl] = g_acc[((size_t)b * 262144 + s0 + s) * 64 + sl];
    }
    __syncthreads();
    #pragma unroll
    for (int i = 0; i < 16; i++) {
        const int c = ch + i * 4;
        const size_t oa = ((size_t)(b * 64 + c)) * 262144 + s0 + sl;
        const float a = ts[sl][c];
        Y[oa] = X[oa] + (a > 0.f ? a : 0.01f * a);
    }
}

extern "C" void kernel_launch(void* const* d_in, const int* in_sizes, int n_in,
                              void* d_out, int out_size)
{
    const float* x    = (const float*)d_in[0];
    const float* w_d  = (const float*)d_in[1];
    const float* b_d  = (const float*)d_in[2];
    const float* w_h  = (const float*)d_in[3];
    const float* b_h  = (const float*)d_in[4];
    const float* w_w  = (const float*)d_in[5];
    const float* b_w  = (const float*)d_in[6];
    const float* w_pd = (const float*)d_in[7];
    const float* b_pd = (const float*)d_in[8];
    const float* w_ph = (const float*)d_in[9];
    const float* b_ph = (const float*)d_in[10];
    const float* w_pw = (const float*)d_in[11];
    const float* b_pw = (const float*)d_in[12];

    cudaFuncSetAttribute(axial_mma, cudaFuncAttributeMaxDynamicSharedMemorySize, DYN_SMEM);

    const int OW_D = 0, OW_H = 1048576, OW_W = 2097152;
    const int OW_PD = 3145728, OW_PH = 3211264, OW_PW = 3276800;

    prep_x<<<8192, 256>>>(x);
    prep_w<<<1024, 256>>>(w_d,  OW_D,  1024);
    prep_w<<<1024, 256>>>(w_h,  OW_H,  1024);
    prep_w<<<1024, 256>>>(w_w,  OW_W,  1024);
    prep_w<<<256,  256>>>(w_pd, OW_PD, 256);
    prep_w<<<256,  256>>>(w_ph, OW_PH, 256);
    prep_w<<<256,  256>>>(w_pw, OW_PW, 256);

    // m-dims (sizes, spatial-row strides incl. b=262144), fastest first
    Dims6 dD = {{4,4,4,16,16,2},  {1,4,16,64,1024,262144}};    // axis d (str 16384)
    Dims6 dH = {{4,4,4,16,16,2},  {1,4,16,64,16384,262144}};   // axis h (str 1024)
    Dims6 dW = {{4,4,4,16,16,2},  {1,4,16,1024,16384,262144}}; // axis w (str 64)
    Dims6 dP = {{4,4,16,16,16,2}, {1,4,64,1024,16384,262144}}; // axis p (str 16)
    Dims6 dQ = {{4,4,16,16,16,2}, {1,16,64,1024,16384,262144}};// axis q (str 4)
    Dims6 dR = {{4,4,16,16,16,2}, {4,16,64,1024,16384,262144}};// axis r (str 1)

    // patch ops: N=256 -> grid (2,1024); image ops: N=1024 -> grid (8,256)
    axial_mma<<<dim3(2, 1024), 256, DYN_SMEM>>>(OW_PD, b_pd, dP, 256, 16,    1);
    axial_mma<<<dim3(2, 1024), 256, DYN_SMEM>>>(OW_PH, b_ph, dQ, 256, 4,     0);
    axial_mma<<<dim3(2, 1024), 256, DYN_SMEM>>>(OW_PW, b_pw, dR, 256, 1,     0);
    axial_mma<<<dim3(8, 256),  256, DYN_SMEM>>>(OW_D,  b_d,  dD, 1024, 16384, 0);
    axial_mma<<<dim3(8, 256),  256, DYN_SMEM>>>(OW_H,  b_h,  dH, 1024, 1024,  0);
    axial_mma<<<dim3(8, 256),  256, DYN_SMEM>>>(OW_W,  b_w,  dW, 1024, 64,    0);

    finalize2<<<8192, 256>>>(x, (float*)d_out);
}